// round 1
// baseline (speedup 1.0000x reference)
#include <cuda_runtime.h>

// Contour_to_mask: winding-number style mask from 8 contours of 64 vertices
// onto a 256x256 grid. out[b,n,i,j] = clip(|sum_k sign_k * angle_k| / 2pi, 0, 1)
//   diff_k  = c_k     - p,   rd_k = c_{k+1} - p   (p = (i/256, j/256))
//   sign_k  = tanh(K * (diff.y*rd.x - diff.x*rd.y))
//   angle_k = acos(clip(dot(diff,rd)/(|diff||rd|), -1+eps, 1-eps))

#define MSIZE   256
#define KV      64
#define NCONT   8
#define KCONST  100000.0f
#define EPSC    1e-5f

__global__ void __launch_bounds__(256) contour_mask_kernel(
    const float* __restrict__ contour,   // [NCONT, KV, 2]
    float* __restrict__ out)             // [NCONT, MSIZE, MSIZE]
{
    __shared__ float4 v[KV];  // (cx, cy, next_cx, next_cy)

    const int c = blockIdx.y;
    const float* cc = contour + c * (KV * 2);
    const int t = threadIdx.x;

    if (t < KV) {
        const int kn = (t + 1) & (KV - 1);
        v[t] = make_float4(cc[2 * t], cc[2 * t + 1], cc[2 * kn], cc[2 * kn + 1]);
    }
    __syncthreads();

    const int pix = blockIdx.x * blockDim.x + t;
    const float x = (float)(pix >> 8)   * (1.0f / MSIZE);  // ii (row)
    const float y = (float)(pix & 255)  * (1.0f / MSIZE);  // jj (col)

    float sum = 0.0f;

#pragma unroll 8
    for (int k = 0; k < KV; k++) {
        const float4 q = v[k];
        const float dx = q.x - x;
        const float dy = q.y - y;
        const float rx = q.z - x;
        const float ry = q.w - y;

        const float dot = dx * rx + dy * ry;
        const float cr  = dy * rx - dx * ry;          // s[...,1] - s[...,0]
        const float n2  = (dx * dx + dy * dy) * (rx * rx + ry * ry);

        float inv;
        asm("rsqrt.approx.f32 %0, %1;" : "=f"(inv) : "f"(n2));

        float r = dot * inv;
        r = fminf(fmaxf(r, -1.0f + EPSC), 1.0f - EPSC);
        const float ang = acosf(r);

        float s;
        asm("tanh.approx.f32 %0, %1;" : "=f"(s) : "f"(KCONST * cr));

        sum = fmaf(s, ang, sum);
    }

    out[c * (MSIZE * MSIZE) + pix] = fminf(fabsf(sum) * 0.15915494309189535f, 1.0f);
}

extern "C" void kernel_launch(void* const* d_in, const int* in_sizes, int n_in,
                              void* d_out, int out_size)
{
    const float* contour = (const float*)d_in[0];
    float* out = (float*)d_out;

    dim3 grid((MSIZE * MSIZE) / 256, NCONT);
    contour_mask_kernel<<<grid, 256>>>(contour, out);
}

// round 2
// speedup vs baseline: 1.4381x; 1.4381x over previous
#include <cuda_runtime.h>

// Contour_to_mask via winding angles.
// angle_k = acos(clip(dot/(|d||r|))) == clamp(atan2(|cross|, dot), A0, pi-A0)
// with A0 = acos(1-1e-5). sign_k = tanh(K*cross).
// out = min(|sum_k sign_k*angle_k| / 2pi, 1)
//
// 2 pixels (same row, adjacent cols) per thread; y-dependent math packed f32x2.

#define MSIZE   256
#define KV      64
#define NCONT   8
#define KCONST  100000.0f

typedef unsigned long long ull;

__device__ __forceinline__ ull pk(float lo, float hi) {
    ull r; asm("mov.b64 %0, {%1,%2};" : "=l"(r) : "f"(lo), "f"(hi)); return r;
}
__device__ __forceinline__ void upk(float& lo, float& hi, ull v) {
    asm("mov.b64 {%0,%1}, %2;" : "=f"(lo), "=f"(hi) : "l"(v));
}
__device__ __forceinline__ ull f2add(ull a, ull b) {
    ull d; asm("add.rn.f32x2 %0,%1,%2;" : "=l"(d) : "l"(a), "l"(b)); return d;
}
__device__ __forceinline__ ull f2mul(ull a, ull b) {
    ull d; asm("mul.rn.f32x2 %0,%1,%2;" : "=l"(d) : "l"(a), "l"(b)); return d;
}
__device__ __forceinline__ ull f2fma(ull a, ull b, ull c) {
    ull d; asm("fma.rn.f32x2 %0,%1,%2,%3;" : "=l"(d) : "l"(a), "l"(b), "l"(c)); return d;
}
__device__ __forceinline__ float frcp(float x) {
    float r; asm("rcp.approx.f32 %0,%1;" : "=f"(r) : "f"(x)); return r;
}
__device__ __forceinline__ float ftanh(float x) {
    float r; asm("tanh.approx.f32 %0,%1;" : "=f"(r) : "f"(x)); return r;
}

// atan minimax on [0,1]: atan(a) ~= a*(c0 + c1 s + ... + c5 s^5), s=a*a. |err|~1e-5
#define AT_C0  0.99997726f
#define AT_C1 -0.33262347f
#define AT_C2  0.19354346f
#define AT_C3 -0.11643287f
#define AT_C4  0.05265332f
#define AT_C5 -0.01172120f

#define HPI     1.5707963267948966f
#define UMAX    1.5663241850f          /* pi/2 - acos(1-1e-5) */
#define INV2PI  0.15915494309189535f

__global__ void __launch_bounds__(256) contour_mask_kernel(
    const float* __restrict__ contour,   // [NCONT, KV, 2]
    float* __restrict__ out)             // [NCONT, MSIZE, MSIZE]
{
    __shared__ float sx[KV];
    __shared__ ull   sy2[KV];   // (cy, cy) broadcast pairs

    const int c = blockIdx.y;
    const float* cc = contour + c * (KV * 2);
    const int t = threadIdx.x;

    if (t < KV) {
        sx[t] = cc[2 * t];
        float cy = cc[2 * t + 1];
        sy2[t] = pk(cy, cy);
    }
    __syncthreads();

    const int gid  = blockIdx.x * blockDim.x + t;     // 0 .. 32767
    const int pix0 = gid * 2;
    const float x  = (float)(pix0 >> 8) * (1.0f / MSIZE);
    const float y0 = (float)(pix0 & 255) * (1.0f / MSIZE);
    const float y1 = y0 + (1.0f / MSIZE);

    const ull negyp = pk(-y0, -y1);
    const ull C0 = pk(AT_C0, AT_C0), C1 = pk(AT_C1, AT_C1), C2 = pk(AT_C2, AT_C2);
    const ull C3 = pk(AT_C3, AT_C3), C4 = pk(AT_C4, AT_C4), C5 = pk(AT_C5, AT_C5);
    const ull NM1 = pk(-1.0f, -1.0f);
    const ull HP2 = pk(HPI, HPI);
    const ull KP  = pk(KCONST, KCONST);

    float sum0 = 0.0f, sum1 = 0.0f;

    // k = 0 state (diff_{k+1} = roll_diff_k reuse)
    float dx     = sx[0] - x;
    ull   dyp    = f2add(sy2[0], negyp);
    ull   bcndx  = pk(-dx, -dx);

#pragma unroll 8
    for (int k = 0; k < KV; k++) {
        const int kn = (k + 1) & (KV - 1);
        const float rx = sx[kn] - x;
        const ull  ryp = f2add(sy2[kn], negyp);

        const float drs = dx * rx;
        const ull dotp = f2fma(dyp, ryp, pk(drs, drs));           // dot = dx*rx + dy*ry
        const ull crp  = f2fma(dyp, pk(rx, rx), f2mul(bcndx, ryp)); // cr = dy*rx - dx*ry

        float cr0, cr1, d0, d1;
        upk(cr0, cr1, crp); upk(d0, d1, dotp);

        const float A0f = fabsf(cr0), D0 = fabsf(d0);
        const float A1f = fabsf(cr1), D1 = fabsf(d1);
        const float mn0 = fminf(A0f, D0), mx0 = fmaxf(A0f, D0);
        const float mn1 = fminf(A1f, D1), mx1 = fmaxf(A1f, D1);

        const float a0 = mn0 * frcp(mx0);
        const float a1 = mn1 * frcp(mx1);

        const ull ap = pk(a0, a1);
        const ull s2 = f2mul(ap, ap);
        ull p = f2fma(s2, C5, C4);
        p = f2fma(p, s2, C3);
        p = f2fma(p, s2, C2);
        p = f2fma(p, s2, C1);
        p = f2fma(p, s2, C0);
        const ull atnp = f2mul(p, ap);              // atan(mn/mx) in [0, pi/4]
        const ull tp   = f2fma(atnp, NM1, HP2);     // pi/2 - atan

        float at0, at1, t0, t1;
        upk(at0, at1, atnp); upk(t0, t1, tp);

        // angle = pi/2 - copysign(u, dot);  u = (|cr|>|dot|) ? atan : pi/2-atan
        // ref clip(r,±(1-1e-5)) == clamp(angle,[A0,pi-A0]) == single min on u
        float u0 = (A0f > D0) ? at0 : t0;
        float u1 = (A1f > D1) ? at1 : t1;
        u0 = fminf(u0, UMAX);
        u1 = fminf(u1, UMAX);

        const float cs0 = __int_as_float(__float_as_int(u0) |
                                         (__float_as_int(d0) & 0x80000000u));
        const float cs1 = __int_as_float(__float_as_int(u1) |
                                         (__float_as_int(d1) & 0x80000000u));
        const float ang0 = HPI - cs0;
        const float ang1 = HPI - cs1;

        float q0, q1;
        const ull kcr = f2mul(KP, crp);
        upk(q0, q1, kcr);
        sum0 = fmaf(ftanh(q0), ang0, sum0);
        sum1 = fmaf(ftanh(q1), ang1, sum1);

        // rotate state
        dx = rx;
        dyp = ryp;
        bcndx = pk(-rx, -rx);
    }

    float2 o;
    o.x = fminf(fabsf(sum0) * INV2PI, 1.0f);
    o.y = fminf(fabsf(sum1) * INV2PI, 1.0f);
    ((float2*)out)[c * (MSIZE * MSIZE / 2) + gid] = o;
}

extern "C" void kernel_launch(void* const* d_in, const int* in_sizes, int n_in,
                              void* d_out, int out_size)
{
    const float* contour = (const float*)d_in[0];
    float* out = (float*)d_out;

    dim3 grid((MSIZE * MSIZE) / (2 * 256), NCONT);
    contour_mask_kernel<<<grid, 256>>>(contour, out);
}